// round 1
// baseline (speedup 1.0000x reference)
#include <cuda_runtime.h>
#include <cuda_bf16.h>
#include <cstdint>

// Problem constants
#define BATCH 4
#define HEADS 16
#define SEQ   2048
#define HDIM  64
#define DMODEL 1024          // HEADS*HDIM
#define LN_EPS 1e-5f

// Attention tiling
#define BM 64                // query rows per block
#define BN 64                // keys per tile
#define NTILES (SEQ / BN)    // 32

// Scratch for attention output, [B, N, D] with heads re-interleaved
__device__ float g_attn[(size_t)BATCH * SEQ * DMODEL];

// ---------------------------------------------------------------------------
// Kernel 1: flash attention, fp32.
// grid: (SEQ/BM, BATCH*HEADS), block: 256 threads.
// smem: Qs[64][65] | KPs[64][65] (K tile, reused as P tile) | Vs[64][64]
// Thread layout: 16x16; each thread owns a 4x4 micro-tile.
// ---------------------------------------------------------------------------
#define SM_QS   0
#define SM_KPS  (64 * 65)
#define SM_VS   (2 * 64 * 65)
#define SMEM_FLOATS (2 * 64 * 65 + 64 * 64)
#define SMEM_BYTES  (SMEM_FLOATS * 4)

__global__ void __launch_bounds__(256, 4)
attn_kernel(const float* __restrict__ q,
            const float* __restrict__ k,
            const float* __restrict__ v)
{
    extern __shared__ float sm[];
    float* Qs  = sm + SM_QS;    // [64][65]
    float* KPs = sm + SM_KPS;   // [64][65]
    float* Vs  = sm + SM_VS;    // [64][64]

    const int bh = blockIdx.y;
    const int b  = bh / HEADS;
    const int h  = bh % HEADS;
    const int qt = blockIdx.x;               // query tile
    const int tid = threadIdx.x;
    const int tx = tid & 15;                 // col group (0..15)
    const int ty = tid >> 4;                 // row group (0..15)

    const float scale = 0.125f;              // 1/sqrt(64)

    // Load Q tile (scaled)
    const float* qbase = q + ((size_t)(b * SEQ + qt * BM)) * DMODEL + h * HDIM;
    #pragma unroll
    for (int i = tid; i < BM * HDIM; i += 256) {
        int r = i >> 6, d = i & 63;
        Qs[r * 65 + d] = qbase[(size_t)r * DMODEL + d] * scale;
    }

    float mrow[4], lrow[4], accO[4][4];
    #pragma unroll
    for (int i = 0; i < 4; i++) {
        mrow[i] = -1e30f; lrow[i] = 0.0f;
        #pragma unroll
        for (int j = 0; j < 4; j++) accO[i][j] = 0.0f;
    }

    const float* kbase = k + ((size_t)b * SEQ) * DMODEL + h * HDIM;
    const float* vbase = v + ((size_t)b * SEQ) * DMODEL + h * HDIM;

    for (int t = 0; t < NTILES; t++) {
        __syncthreads();   // prior P/V consumption done -> safe to overwrite
        // Load K, V tiles
        #pragma unroll
        for (int i = tid; i < BN * HDIM; i += 256) {
            int r = i >> 6, d = i & 63;
            size_t goff = (size_t)(t * BN + r) * DMODEL + d;
            KPs[r * 65 + d] = kbase[goff];
            Vs [r * 64 + d] = vbase[goff];
        }
        __syncthreads();

        // S = (Q*scale) K^T  -- 4x4 per thread
        float s[4][4];
        #pragma unroll
        for (int i = 0; i < 4; i++)
            #pragma unroll
            for (int j = 0; j < 4; j++) s[i][j] = 0.0f;

        #pragma unroll 4
        for (int kk = 0; kk < HDIM; kk++) {
            float a[4], bb[4];
            #pragma unroll
            for (int i = 0; i < 4; i++) a[i]  = Qs [(ty * 4 + i) * 65 + kk];
            #pragma unroll
            for (int j = 0; j < 4; j++) bb[j] = KPs[(tx * 4 + j) * 65 + kk];
            #pragma unroll
            for (int i = 0; i < 4; i++)
                #pragma unroll
                for (int j = 0; j < 4; j++)
                    s[i][j] = fmaf(a[i], bb[j], s[i][j]);
        }
        __syncthreads();   // all threads done reading K tile; KPs becomes P tile

        // Online softmax update; write P into KPs
        #pragma unroll
        for (int i = 0; i < 4; i++) {
            float rm = fmaxf(fmaxf(s[i][0], s[i][1]), fmaxf(s[i][2], s[i][3]));
            #pragma unroll
            for (int off = 8; off > 0; off >>= 1)
                rm = fmaxf(rm, __shfl_xor_sync(0xffffffffu, rm, off, 16));
            float mnew = fmaxf(mrow[i], rm);
            float corr = __expf(mrow[i] - mnew);
            float psum = 0.0f;
            #pragma unroll
            for (int j = 0; j < 4; j++) {
                float p = __expf(s[i][j] - mnew);
                psum += p;
                KPs[(ty * 4 + i) * 65 + (tx * 4 + j)] = p;
            }
            #pragma unroll
            for (int off = 8; off > 0; off >>= 1)
                psum += __shfl_xor_sync(0xffffffffu, psum, off, 16);
            lrow[i] = lrow[i] * corr + psum;
            mrow[i] = mnew;
            #pragma unroll
            for (int j = 0; j < 4; j++) accO[i][j] *= corr;
        }
        __syncthreads();

        // O += P @ V   (thread owns rows ty*4+i, dims tx*4+j)
        #pragma unroll 4
        for (int jj = 0; jj < BN; jj++) {
            float pv[4], vv[4];
            #pragma unroll
            for (int i = 0; i < 4; i++) pv[i] = KPs[(ty * 4 + i) * 65 + jj];
            #pragma unroll
            for (int j = 0; j < 4; j++) vv[j] = Vs[jj * 64 + tx * 4 + j];
            #pragma unroll
            for (int i = 0; i < 4; i++)
                #pragma unroll
                for (int j = 0; j < 4; j++)
                    accO[i][j] = fmaf(pv[i], vv[j], accO[i][j]);
        }
    }

    // Normalize and write to scratch [b, n, h*64+d]
    float* obase = g_attn + ((size_t)(b * SEQ + qt * BM)) * DMODEL + h * HDIM;
    #pragma unroll
    for (int i = 0; i < 4; i++) {
        float inv = 1.0f / lrow[i];
        #pragma unroll
        for (int j = 0; j < 4; j++)
            obase[(size_t)(ty * 4 + i) * DMODEL + tx * 4 + j] = accO[i][j] * inv;
    }
}

// ---------------------------------------------------------------------------
// Kernel 2: projection  out = X @ W^T  (X = g_attn [8192,1024], W [1024,1024])
// grid: (DMODEL/64, BATCH*SEQ/64), block 256, 4x4 micro-tiles, K-tile 32.
// ---------------------------------------------------------------------------
__global__ void __launch_bounds__(256, 4)
proj_kernel(const float* __restrict__ W, float* __restrict__ out)
{
    __shared__ float Xs[64][33];
    __shared__ float Ws[64][33];

    const int tid = threadIdx.x;
    const int tx = tid & 15, ty = tid >> 4;
    const int rowBase = blockIdx.y * 64;
    const int colBase = blockIdx.x * 64;

    float acc[4][4];
    #pragma unroll
    for (int i = 0; i < 4; i++)
        #pragma unroll
        for (int j = 0; j < 4; j++) acc[i][j] = 0.0f;

    for (int kt = 0; kt < DMODEL / 32; kt++) {
        #pragma unroll
        for (int i = tid; i < 64 * 32; i += 256) {
            int r = i >> 5, kk = i & 31;
            Xs[r][kk] = g_attn[(size_t)(rowBase + r) * DMODEL + kt * 32 + kk];
            Ws[r][kk] = W[(size_t)(colBase + r) * DMODEL + kt * 32 + kk];
        }
        __syncthreads();
        #pragma unroll 8
        for (int kk = 0; kk < 32; kk++) {
            float a[4], bb[4];
            #pragma unroll
            for (int i = 0; i < 4; i++) a[i]  = Xs[ty * 4 + i][kk];
            #pragma unroll
            for (int j = 0; j < 4; j++) bb[j] = Ws[tx * 4 + j][kk];
            #pragma unroll
            for (int i = 0; i < 4; i++)
                #pragma unroll
                for (int j = 0; j < 4; j++)
                    acc[i][j] = fmaf(a[i], bb[j], acc[i][j]);
        }
        __syncthreads();
    }

    #pragma unroll
    for (int i = 0; i < 4; i++)
        #pragma unroll
        for (int j = 0; j < 4; j++)
            out[(size_t)(rowBase + ty * 4 + i) * DMODEL + colBase + tx * 4 + j] = acc[i][j];
}

// ---------------------------------------------------------------------------
// Kernel 3: in-place row LayerNorm (bias-free), row = 1024 floats.
// grid: BATCH*SEQ blocks, 256 threads; each thread owns one float4.
// ---------------------------------------------------------------------------
__global__ void __launch_bounds__(256)
ln_kernel(float* __restrict__ out, const float* __restrict__ g)
{
    const int row = blockIdx.x;
    float* p = out + (size_t)row * DMODEL;
    const int tid = threadIdx.x;

    float4 x = reinterpret_cast<float4*>(p)[tid];
    float s  = x.x + x.y + x.z + x.w;
    float ss = x.x * x.x + x.y * x.y + x.z * x.z + x.w * x.w;

    #pragma unroll
    for (int off = 16; off > 0; off >>= 1) {
        s  += __shfl_xor_sync(0xffffffffu, s,  off);
        ss += __shfl_xor_sync(0xffffffffu, ss, off);
    }
    __shared__ float sbuf[8], ssbuf[8];
    if ((tid & 31) == 0) { sbuf[tid >> 5] = s; ssbuf[tid >> 5] = ss; }
    __syncthreads();
    s = 0.0f; ss = 0.0f;
    #pragma unroll
    for (int i = 0; i < 8; i++) { s += sbuf[i]; ss += ssbuf[i]; }

    const float mean = s * (1.0f / DMODEL);
    const float var  = ss * (1.0f / DMODEL) - mean * mean;
    const float rstd = rsqrtf(var + LN_EPS);

    float4 gv = reinterpret_cast<const float4*>(g)[tid];
    x.x = (x.x - mean) * rstd * gv.x;
    x.y = (x.y - mean) * rstd * gv.y;
    x.z = (x.z - mean) * rstd * gv.z;
    x.w = (x.w - mean) * rstd * gv.w;
    reinterpret_cast<float4*>(p)[tid] = x;
}

// ---------------------------------------------------------------------------
extern "C" void kernel_launch(void* const* d_in, const int* in_sizes, int n_in,
                              void* d_out, int out_size)
{
    const float* q  = (const float*)d_in[0];
    const float* k  = (const float*)d_in[1];
    const float* v  = (const float*)d_in[2];
    const float* W  = (const float*)d_in[3];
    const float* g  = (const float*)d_in[4];
    float* out = (float*)d_out;

    cudaFuncSetAttribute(attn_kernel,
                         cudaFuncAttributeMaxDynamicSharedMemorySize, SMEM_BYTES);

    dim3 ablock(256), agrid(SEQ / BM, BATCH * HEADS);
    attn_kernel<<<agrid, ablock, SMEM_BYTES>>>(q, k, v);

    dim3 pgrid(DMODEL / 64, BATCH * SEQ / 64);
    proj_kernel<<<pgrid, 256>>>(W, out);

    ln_kernel<<<BATCH * SEQ, 256>>>(out, g);
}

// round 2
// speedup vs baseline: 3.6072x; 3.6072x over previous
#include <cuda_runtime.h>
#include <cuda_bf16.h>
#include <cstdint>

// Problem constants
#define BATCH 4
#define HEADS 16
#define SEQ   2048
#define HDIM  64
#define DMODEL 1024
#define LN_EPS 1e-5f

// Attention tiling
#define BM 64
#define BN 64
#define NTILES (SEQ / BN)

// Smem row pads (floats). Chosen so every mma fragment access pattern is
// bank-conflict-free:
//  A/B frags on Q/K/P: addr = row*68 + col -> bank = (4*row + col) mod 32, row in 0..7, col in 0..3 union +4 : all distinct.
//  B frags on V:       addr = k*72 + n     -> bank = (8*k + n) mod 32, k in 0..3(+4), n in 0..7 : all distinct.
#define LQ  68
#define LKP 68
#define LV  72
#define ATT_SMEM_FLOATS (64*LQ + 64*LKP + 64*LV)
#define ATT_SMEM_BYTES  (ATT_SMEM_FLOATS * 4)

// Scratch: attention output [B, N, D] (heads re-interleaved)
__device__ float g_attn[(size_t)BATCH * SEQ * DMODEL];

// ---- helpers --------------------------------------------------------------
__device__ __forceinline__ float tf(float x) {            // round-to-nearest tf32
    uint32_t u;
    asm("cvt.rna.tf32.f32 %0, %1;" : "=r"(u) : "f"(x));
    return __uint_as_float(u);
}
__device__ __forceinline__ uint32_t fu(float x) { return __float_as_uint(x); }

__device__ __forceinline__ void mma_tf32(float c[4],
                                         uint32_t a0, uint32_t a1, uint32_t a2, uint32_t a3,
                                         uint32_t b0, uint32_t b1) {
    asm volatile(
        "mma.sync.aligned.m16n8k8.row.col.f32.tf32.tf32.f32 "
        "{%0,%1,%2,%3}, {%4,%5,%6,%7}, {%8,%9}, {%0,%1,%2,%3};\n"
        : "+f"(c[0]), "+f"(c[1]), "+f"(c[2]), "+f"(c[3])
        : "r"(a0), "r"(a1), "r"(a2), "r"(a3), "r"(b0), "r"(b1));
}

// ---------------------------------------------------------------------------
// Kernel 1: flash attention, tf32 tensor cores.
// grid (SEQ/BM, B*H), block 128 (4 warps). Warp w owns 16 query rows.
// ---------------------------------------------------------------------------
__global__ void __launch_bounds__(128)
attn_kernel(const float* __restrict__ q,
            const float* __restrict__ k,
            const float* __restrict__ v)
{
    extern __shared__ float sm[];
    float* Qs  = sm;                      // [64][LQ]  tf32
    float* KPs = sm + 64 * LQ;            // [64][LKP] K tile, then P tile
    float* Vs  = sm + 64 * LQ + 64 * LKP; // [64][LV]

    const int bh = blockIdx.y;
    const int b  = bh >> 4;
    const int h  = bh & 15;
    const int qt = blockIdx.x;
    const int tid  = threadIdx.x;
    const int lane = tid & 31;
    const int w    = tid >> 5;
    const int g    = lane >> 2;   // group id (row within mma tile)
    const int t    = lane & 3;    // thread-in-group (col)
    const int m0   = w * 16;

    const float scale = 0.125f;

    // Load Q tile (scale + tf32 round)
    const float* qb = q + ((size_t)(b * SEQ + qt * BM)) * DMODEL + h * HDIM;
    #pragma unroll
    for (int i = tid; i < 64 * 16; i += 128) {
        int r = i >> 4, c = i & 15;
        float4 x = *reinterpret_cast<const float4*>(qb + (size_t)r * DMODEL + c * 4);
        float4 y;
        y.x = tf(x.x * scale); y.y = tf(x.y * scale);
        y.z = tf(x.z * scale); y.w = tf(x.w * scale);
        *reinterpret_cast<float4*>(Qs + r * LQ + c * 4) = y;
    }

    float o[8][4];
    #pragma unroll
    for (int n = 0; n < 8; n++)
        #pragma unroll
        for (int j = 0; j < 4; j++) o[n][j] = 0.0f;
    float mrow[2] = {-1e30f, -1e30f};
    float lrow[2] = {0.0f, 0.0f};

    const float* kb0 = k + ((size_t)b * SEQ) * DMODEL + h * HDIM;
    const float* vb0 = v + ((size_t)b * SEQ) * DMODEL + h * HDIM;

    for (int ti = 0; ti < NTILES; ti++) {
        __syncthreads();   // previous tile's P/V consumption complete
        const float* kb = kb0 + (size_t)(ti * BN) * DMODEL;
        const float* vb = vb0 + (size_t)(ti * BN) * DMODEL;
        #pragma unroll
        for (int i = tid; i < 64 * 16; i += 128) {
            int r = i >> 4, c = i & 15;
            float4 xk = *reinterpret_cast<const float4*>(kb + (size_t)r * DMODEL + c * 4);
            float4 xv = *reinterpret_cast<const float4*>(vb + (size_t)r * DMODEL + c * 4);
            float4 yk, yv;
            yk.x = tf(xk.x); yk.y = tf(xk.y); yk.z = tf(xk.z); yk.w = tf(xk.w);
            yv.x = tf(xv.x); yv.y = tf(xv.y); yv.z = tf(xv.z); yv.w = tf(xv.w);
            *reinterpret_cast<float4*>(KPs + r * LKP + c * 4) = yk;
            *reinterpret_cast<float4*>(Vs  + r * LV  + c * 4) = yv;
        }
        __syncthreads();

        // ---- S = Q K^T -----------------------------------------------------
        float s[8][4];
        #pragma unroll
        for (int n = 0; n < 8; n++)
            #pragma unroll
            for (int j = 0; j < 4; j++) s[n][j] = 0.0f;

        #pragma unroll
        for (int ks = 0; ks < 8; ks++) {
            uint32_t a0 = fu(Qs[(m0 + g)     * LQ + ks * 8 + t]);
            uint32_t a1 = fu(Qs[(m0 + g + 8) * LQ + ks * 8 + t]);
            uint32_t a2 = fu(Qs[(m0 + g)     * LQ + ks * 8 + t + 4]);
            uint32_t a3 = fu(Qs[(m0 + g + 8) * LQ + ks * 8 + t + 4]);
            #pragma unroll
            for (int n = 0; n < 8; n++) {
                uint32_t b0 = fu(KPs[(n * 8 + g) * LKP + ks * 8 + t]);
                uint32_t b1 = fu(KPs[(n * 8 + g) * LKP + ks * 8 + t + 4]);
                mma_tf32(s[n], a0, a1, a2, a3, b0, b1);
            }
        }
        __syncthreads();   // all warps done reading K; KPs becomes P

        // ---- online softmax; write P (tf32) into KPs -----------------------
        #pragma unroll
        for (int slot = 0; slot < 2; slot++) {
            const int c0 = slot * 2, c1 = slot * 2 + 1;
            float rmax = -1e30f;
            #pragma unroll
            for (int n = 0; n < 8; n++)
                rmax = fmaxf(rmax, fmaxf(s[n][c0], s[n][c1]));
            rmax = fmaxf(rmax, __shfl_xor_sync(0xffffffffu, rmax, 1, 4));
            rmax = fmaxf(rmax, __shfl_xor_sync(0xffffffffu, rmax, 2, 4));
            float mnew = fmaxf(mrow[slot], rmax);
            float corr = __expf(mrow[slot] - mnew);
            float psum = 0.0f;
            const int prow = (m0 + g + slot * 8) * LKP;
            #pragma unroll
            for (int n = 0; n < 8; n++) {
                float p0 = __expf(s[n][c0] - mnew);
                float p1 = __expf(s[n][c1] - mnew);
                psum += p0 + p1;
                *reinterpret_cast<float2*>(KPs + prow + n * 8 + 2 * t) =
                    make_float2(tf(p0), tf(p1));
            }
            psum += __shfl_xor_sync(0xffffffffu, psum, 1, 4);
            psum += __shfl_xor_sync(0xffffffffu, psum, 2, 4);
            lrow[slot] = lrow[slot] * corr + psum;
            mrow[slot] = mnew;
            #pragma unroll
            for (int n = 0; n < 8; n++) { o[n][c0] *= corr; o[n][c1] *= corr; }
        }
        __syncthreads();

        // ---- O += P V ------------------------------------------------------
        #pragma unroll
        for (int ks = 0; ks < 8; ks++) {
            uint32_t a0 = fu(KPs[(m0 + g)     * LKP + ks * 8 + t]);
            uint32_t a1 = fu(KPs[(m0 + g + 8) * LKP + ks * 8 + t]);
            uint32_t a2 = fu(KPs[(m0 + g)     * LKP + ks * 8 + t + 4]);
            uint32_t a3 = fu(KPs[(m0 + g + 8) * LKP + ks * 8 + t + 4]);
            #pragma unroll
            for (int n = 0; n < 8; n++) {
                uint32_t b0 = fu(Vs[(ks * 8 + t)     * LV + n * 8 + g]);
                uint32_t b1 = fu(Vs[(ks * 8 + t + 4) * LV + n * 8 + g]);
                mma_tf32(o[n], a0, a1, a2, a3, b0, b1);
            }
        }
    }

    // Epilogue: normalize, write scratch
    float inv0 = 1.0f / lrow[0];
    float inv1 = 1.0f / lrow[1];
    float* ob = g_attn + ((size_t)(b * SEQ + qt * BM + m0)) * DMODEL + h * HDIM;
    #pragma unroll
    for (int n = 0; n < 8; n++) {
        *reinterpret_cast<float2*>(ob + (size_t)g * DMODEL + n * 8 + 2 * t) =
            make_float2(o[n][0] * inv0, o[n][1] * inv0);
        *reinterpret_cast<float2*>(ob + (size_t)(g + 8) * DMODEL + n * 8 + 2 * t) =
            make_float2(o[n][2] * inv1, o[n][3] * inv1);
    }
}

// ---------------------------------------------------------------------------
// Kernel 2: projection out = X @ W^T, tf32 tensor cores.
// Tile 128(M) x 64(N), Kchunk 32. Block 256 threads (8 warps, m16 each).
// ---------------------------------------------------------------------------
#define LX 36
#define LW 36

__global__ void __launch_bounds__(256)
proj_kernel(const float* __restrict__ W, float* __restrict__ out)
{
    __shared__ float Xs[128 * LX];
    __shared__ float Ws[64 * LW];

    const int tid  = threadIdx.x;
    const int lane = tid & 31;
    const int w    = tid >> 5;
    const int g    = lane >> 2;
    const int t    = lane & 3;
    const int m0   = w * 16;
    const int rowBase = blockIdx.y * 128;
    const int colBase = blockIdx.x * 64;

    float acc[8][4];
    #pragma unroll
    for (int n = 0; n < 8; n++)
        #pragma unroll
        for (int j = 0; j < 4; j++) acc[n][j] = 0.0f;

    for (int kt = 0; kt < DMODEL / 32; kt++) {
        #pragma unroll
        for (int i = tid; i < 128 * 8; i += 256) {     // X: 128 rows x 8 float4
            int r = i >> 3, c = i & 7;
            float4 x = *reinterpret_cast<const float4*>(
                g_attn + (size_t)(rowBase + r) * DMODEL + kt * 32 + c * 4);
            float4 y;
            y.x = tf(x.x); y.y = tf(x.y); y.z = tf(x.z); y.w = tf(x.w);
            *reinterpret_cast<float4*>(Xs + r * LX + c * 4) = y;
        }
        #pragma unroll
        for (int i = tid; i < 64 * 8; i += 256) {      // W: 64 rows x 8 float4
            int r = i >> 3, c = i & 7;
            float4 x = *reinterpret_cast<const float4*>(
                W + (size_t)(colBase + r) * DMODEL + kt * 32 + c * 4);
            float4 y;
            y.x = tf(x.x); y.y = tf(x.y); y.z = tf(x.z); y.w = tf(x.w);
            *reinterpret_cast<float4*>(Ws + r * LW + c * 4) = y;
        }
        __syncthreads();

        #pragma unroll
        for (int ks = 0; ks < 4; ks++) {
            uint32_t a0 = fu(Xs[(m0 + g)     * LX + ks * 8 + t]);
            uint32_t a1 = fu(Xs[(m0 + g + 8) * LX + ks * 8 + t]);
            uint32_t a2 = fu(Xs[(m0 + g)     * LX + ks * 8 + t + 4]);
            uint32_t a3 = fu(Xs[(m0 + g + 8) * LX + ks * 8 + t + 4]);
            #pragma unroll
            for (int n = 0; n < 8; n++) {
                uint32_t b0 = fu(Ws[(n * 8 + g) * LW + ks * 8 + t]);
                uint32_t b1 = fu(Ws[(n * 8 + g) * LW + ks * 8 + t + 4]);
                mma_tf32(acc[n], a0, a1, a2, a3, b0, b1);
            }
        }
        __syncthreads();
    }

    float* ob = out + (size_t)(rowBase + m0) * DMODEL + colBase;
    #pragma unroll
    for (int n = 0; n < 8; n++) {
        *reinterpret_cast<float2*>(ob + (size_t)g * DMODEL + n * 8 + 2 * t) =
            make_float2(acc[n][0], acc[n][1]);
        *reinterpret_cast<float2*>(ob + (size_t)(g + 8) * DMODEL + n * 8 + 2 * t) =
            make_float2(acc[n][2], acc[n][3]);
    }
}

// ---------------------------------------------------------------------------
// Kernel 3: in-place row LayerNorm (bias-free), row = 1024 floats.
// ---------------------------------------------------------------------------
__global__ void __launch_bounds__(256)
ln_kernel(float* __restrict__ out, const float* __restrict__ g)
{
    const int row = blockIdx.x;
    float* p = out + (size_t)row * DMODEL;
    const int tid = threadIdx.x;

    float4 x = reinterpret_cast<float4*>(p)[tid];
    float s  = x.x + x.y + x.z + x.w;
    float ss = x.x * x.x + x.y * x.y + x.z * x.z + x.w * x.w;

    #pragma unroll
    for (int off = 16; off > 0; off >>= 1) {
        s  += __shfl_xor_sync(0xffffffffu, s,  off);
        ss += __shfl_xor_sync(0xffffffffu, ss, off);
    }
    __shared__ float sbuf[8], ssbuf[8];
    if ((tid & 31) == 0) { sbuf[tid >> 5] = s; ssbuf[tid >> 5] = ss; }
    __syncthreads();
    s = 0.0f; ss = 0.0f;
    #pragma unroll
    for (int i = 0; i < 8; i++) { s += sbuf[i]; ss += ssbuf[i]; }

    const float mean = s * (1.0f / DMODEL);
    const float var  = ss * (1.0f / DMODEL) - mean * mean;
    const float rstd = rsqrtf(var + LN_EPS);

    float4 gv = reinterpret_cast<const float4*>(g)[tid];
    x.x = (x.x - mean) * rstd * gv.x;
    x.y = (x.y - mean) * rstd * gv.y;
    x.z = (x.z - mean) * rstd * gv.z;
    x.w = (x.w - mean) * rstd * gv.w;
    reinterpret_cast<float4*>(p)[tid] = x;
}

// ---------------------------------------------------------------------------
extern "C" void kernel_launch(void* const* d_in, const int* in_sizes, int n_in,
                              void* d_out, int out_size)
{
    const float* q  = (const float*)d_in[0];
    const float* k  = (const float*)d_in[1];
    const float* v  = (const float*)d_in[2];
    const float* W  = (const float*)d_in[3];
    const float* g  = (const float*)d_in[4];
    float* out = (float*)d_out;

    cudaFuncSetAttribute(attn_kernel,
                         cudaFuncAttributeMaxDynamicSharedMemorySize, ATT_SMEM_BYTES);

    dim3 agrid(SEQ / BM, BATCH * HEADS);
    attn_kernel<<<agrid, 128, ATT_SMEM_BYTES>>>(q, k, v);

    dim3 pgrid(DMODEL / 64, BATCH * SEQ / 128);
    proj_kernel<<<pgrid, 256>>>(W, out);

    ln_kernel<<<BATCH * SEQ, 256>>>(out, g);
}